// round 12
// baseline (speedup 1.0000x reference)
#include <cuda_runtime.h>
#include <cuda_bf16.h>
#include <cstdint>

#define B_TOTAL  16384
#define K_DIM    4096
#define F_EPS    1.1920929e-07f

#define ROWS_CTA 64
#define KT       64
#define NTILES   (K_DIM / KT)          // 64
#define STAGES   4
#define SX_B     288
#define SW_B     144
#define X_STAGE_B (ROWS_CTA * SX_B)    // 18432
#define W_STAGE_B (32 * SW_B)          // 4608
#define STAGE_B   (X_STAGE_B + W_STAGE_B)  // 23040
#define SMEM_B    (STAGES * STAGE_B)   // 92160

#define DOTS_BLOCKS_TOTAL (B_TOTAL / ROWS_CTA)   // 256
#define CHUNK_DOTS   64                           // dots blocks per chunk (4096 rows)
#define CHUNK_ROWS   (CHUNK_DOTS * ROWS_CTA)      // 4096
#define K3_CTAS      (CHUNK_ROWS / 4)             // 1024 (4 rows per CTA, warp/row)

__device__ __nv_bfloat16 g_Wb[32 * K_DIM];
__device__ float g_C[B_TOTAL * 16];

__device__ __forceinline__ void ffma2(unsigned long long &acc,
                                      unsigned long long a,
                                      unsigned long long b) {
    asm("fma.rn.f32x2 %0, %1, %2, %0;" : "+l"(acc) : "l"(a), "l"(b));
}
__device__ __forceinline__ float hsum2(unsigned long long v) {
    return __uint_as_float((unsigned)(v & 0xffffffffull)) +
           __uint_as_float((unsigned)(v >> 32));
}
__device__ __forceinline__ void cp_async16(uint32_t saddr, const void* g) {
    asm volatile("cp.async.cg.shared.global [%0], [%1], 16;\n" :: "r"(saddr), "l"(g));
}
__device__ __forceinline__ void cp_commit() {
    asm volatile("cp.async.commit_group;\n");
}
template <int N>
__device__ __forceinline__ void cp_wait() {
    asm volatile("cp.async.wait_group %0;\n" :: "n"(N));
}
__device__ __forceinline__ uint32_t cvt_bf2(float lo, float hi) {
    uint32_t r;
    asm("cvt.rn.bf16x2.f32 %0, %1, %2;" : "=r"(r) : "f"(hi), "f"(lo));
    return r;
}
__device__ __forceinline__ void mma_bf16(float &c0, float &c1, float &c2, float &c3,
                                         uint32_t a0, uint32_t a1, uint32_t a2, uint32_t a3,
                                         uint32_t b0, uint32_t b1) {
    asm volatile(
        "mma.sync.aligned.m16n8k16.row.col.f32.bf16.bf16.f32 "
        "{%0,%1,%2,%3}, {%4,%5,%6,%7}, {%8,%9}, {%0,%1,%2,%3};"
        : "+f"(c0), "+f"(c1), "+f"(c2), "+f"(c3)
        : "r"(a0), "r"(a1), "r"(a2), "r"(a3), "r"(b0), "r"(b1));
}

// ---------------------------------------------------------------------------
// prepass: W fp32 -> bf16
// ---------------------------------------------------------------------------
__global__ __launch_bounds__(256)
void wconv(const float* __restrict__ Wri, const float* __restrict__ Wwo,
           const float* __restrict__ Wsm) {
    const int base = (blockIdx.x * 256 + threadIdx.x) * 4;   // grid 128
    const int d = base / K_DIM;
    const int k = base % K_DIM;
    const float* wrow = (d < 8)  ? (Wri + d * K_DIM)
                      : (d < 16) ? (Wwo + (d - 8) * K_DIM)
                                 : (Wsm + (d - 16) * K_DIM);
    const float4 v = *(const float4*)(wrow + k);
    *(uint2*)(&g_Wb[d * K_DIM + k]) = make_uint2(cvt_bf2(v.x, v.y), cvt_bf2(v.z, v.w));
}

// ---------------------------------------------------------------------------
// dots CTA body (identical math to the proven R10 kernel; row0 parameterized)
// ---------------------------------------------------------------------------
__device__ __forceinline__
void dots_body(char* smc,
               const float* __restrict__ x,
               const float* __restrict__ read_in,  const float* __restrict__ a_ri,
               const float* __restrict__ write_out, const float* __restrict__ a_wo,
               const float* __restrict__ stream_mixing, const float* __restrict__ a_sm,
               int dots_block) {
    const int tid  = threadIdx.x;
    const int warp = tid >> 5;
    const int lane = tid & 31;
    const int row0 = dots_block * ROWS_CTA;

    const uint32_t sbase = (uint32_t)__cvta_generic_to_shared(smc);

    auto fetch = [&](int t) {
        const uint32_t st = sbase + (t & (STAGES - 1)) * STAGE_B;
        const int k0 = t * KT;
#pragma unroll
        for (int i = 0; i < 8; i++) {              // x: 64 rows x 16 quads
            const int f = tid + i * 128;
            const int row = f >> 4, kq = f & 15;
            cp_async16(st + row * SX_B + kq * 16,
                       x + (size_t)(row0 + row) * K_DIM + k0 + kq * 4);
        }
#pragma unroll
        for (int i = 0; i < 2; i++) {              // W: 32 rows x 8 chunks
            const int f2 = tid + i * 128;
            const int d = f2 >> 3, kc = f2 & 7;
            cp_async16(st + X_STAGE_B + d * SW_B + kc * 16,
                       g_Wb + d * K_DIM + k0 + kc * 8);
        }
        cp_commit();
    };

    fetch(0);
    fetch(1);
    fetch(2);

    float c[4][4];
#pragma unroll
    for (int n = 0; n < 4; n++)
#pragma unroll
        for (int j = 0; j < 4; j++) c[n][j] = 0.0f;
    unsigned long long ssa = 0ull, ssb = 0ull;

    const int g  = lane >> 2;
    const int cc = lane & 3;

    for (int t = 0; t < NTILES; t++) {
        cp_wait<STAGES - 2>();
        __syncthreads();
        if (t + 3 < NTILES) fetch(t + 3);

        const char* stage = smc + (t & (STAGES - 1)) * STAGE_B;
        const char* xs = stage;
        const char* ws = stage + X_STAGE_B;

#pragma unroll
        for (int s = 0; s < 4; s++) {
            const int kb = s * 16;
            const char* arow = xs + (warp * 16 + g) * SX_B + (kb + cc * 2) * 4;
            const float2 fa0 = *(const float2*)(arow);
            const float2 fa1 = *(const float2*)(arow + 8 * SX_B);
            const float2 fa2 = *(const float2*)(arow + 32);
            const float2 fa3 = *(const float2*)(arow + 8 * SX_B + 32);
            const unsigned long long u0 = *(const unsigned long long*)&fa0;
            const unsigned long long u1 = *(const unsigned long long*)&fa1;
            const unsigned long long u2 = *(const unsigned long long*)&fa2;
            const unsigned long long u3 = *(const unsigned long long*)&fa3;
            ffma2(ssa, u0, u0);
            ffma2(ssa, u2, u2);
            ffma2(ssb, u1, u1);
            ffma2(ssb, u3, u3);

            const uint32_t a0 = cvt_bf2(fa0.x, fa0.y);
            const uint32_t a1 = cvt_bf2(fa1.x, fa1.y);
            const uint32_t a2 = cvt_bf2(fa2.x, fa2.y);
            const uint32_t a3 = cvt_bf2(fa3.x, fa3.y);
#pragma unroll
            for (int ng = 0; ng < 4; ng++) {
                const char* brow = ws + (ng * 8 + g) * SW_B + (kb + cc * 2) * 2;
                const uint32_t b0 = *(const uint32_t*)(brow);
                const uint32_t b1 = *(const uint32_t*)(brow + 16);
                mma_bf16(c[ng][0], c[ng][1], c[ng][2], c[ng][3],
                         a0, a1, a2, a3, b0, b1);
            }
        }
    }
    __syncthreads();

    float* Hs  = (float*)smc;                    // [64][32]
    float* SSs = (float*)(smc + 64 * 32 * 4);    // [64]

    {
        const int r0l = warp * 16 + g;
#pragma unroll
        for (int ng = 0; ng < 4; ng++) {
            const int d0 = ng * 8 + cc * 2;
            Hs[r0l * 32 + d0]           = c[ng][0];
            Hs[r0l * 32 + d0 + 1]       = c[ng][1];
            Hs[(r0l + 8) * 32 + d0]     = c[ng][2];
            Hs[(r0l + 8) * 32 + d0 + 1] = c[ng][3];
        }
        float va = hsum2(ssa), vb = hsum2(ssb);
        va += __shfl_xor_sync(0xffffffffu, va, 1);
        va += __shfl_xor_sync(0xffffffffu, va, 2);
        vb += __shfl_xor_sync(0xffffffffu, vb, 1);
        vb += __shfl_xor_sync(0xffffffffu, vb, 2);
        if (cc == 0) {
            SSs[r0l]     = va;
            SSs[r0l + 8] = vb;
        }
    }
    __syncthreads();

    if (tid < ROWS_CTA) {
        const int r = tid;
        const float s = rsqrtf(SSs[r] * (1.0f / (float)K_DIM) + F_EPS);
        float h[32];
#pragma unroll
        for (int d = 0; d < 32; d++) h[d] = Hs[r * 32 + d] * s;

        const float ari = a_ri[0], awo = a_wo[0], asmix = a_sm[0];
        float riT[2][4], wo[4][2], p[4][4];
#pragma unroll
        for (int n = 0; n < 4; n++)
#pragma unroll
            for (int m = 0; m < 2; m++) {
                const float hri = ari * h[n * 2 + m] + read_in[n * 2 + m];
                riT[m][n] = 1.0f / (1.0f + expf(-hri));
                const float hwo = awo * h[8 + n * 2 + m] + write_out[n * 2 + m];
                wo[n][m] = 2.0f / (1.0f + expf(-hwo));
            }
#pragma unroll
        for (int i = 0; i < 4; i++)
#pragma unroll
            for (int j = 0; j < 4; j++)
                p[i][j] = expf(asmix * h[16 + i * 4 + j] + stream_mixing[i * 4 + j]);

        for (int it = 0; it < 20; it++) {
#pragma unroll
            for (int i = 0; i < 4; i++) {
                const float inv = 1.0f / (p[i][0] + p[i][1] + p[i][2] + p[i][3]);
#pragma unroll
                for (int j = 0; j < 4; j++) p[i][j] *= inv;
            }
#pragma unroll
            for (int j = 0; j < 4; j++) {
                const float inv = 1.0f / (p[0][j] + p[1][j] + p[2][j] + p[3][j]);
#pragma unroll
                for (int i = 0; i < 4; i++) p[i][j] *= inv;
            }
        }
#pragma unroll
        for (int n = 0; n < 4; n++)
#pragma unroll
            for (int j = 0; j < 4; j++)
                g_C[(size_t)(row0 + r) * 16 + n * 4 + j] =
                    wo[n][0] * riT[0][j] + wo[n][1] * riT[1][j] + p[n][j];
    }
}

// ---------------------------------------------------------------------------
// k3 warp body: out[row] = C_row @ x[row] (warp handles one full row)
// ---------------------------------------------------------------------------
__device__ __forceinline__
void k3_warp(const float* __restrict__ x, float* __restrict__ out,
             int row, int lane) {
    float cr[4][4];
#pragma unroll
    for (int n = 0; n < 4; n++)
#pragma unroll
        for (int j = 0; j < 4; j++)
            cr[n][j] = __ldg(&g_C[(size_t)row * 16 + n * 4 + j]);

    const float4* xr = (const float4*)(x + (size_t)row * K_DIM);
    float4* orow = (float4*)(out + (size_t)row * K_DIM);

#pragma unroll
    for (int pch = 0; pch < 8; pch++) {
        const int col = pch * 32 + lane;
        float4 xv[4];
#pragma unroll
        for (int j = 0; j < 4; j++) xv[j] = __ldcs(&xr[j * 256 + col]);
#pragma unroll
        for (int n = 0; n < 4; n++) {
            float4 o;
            o.x = cr[n][0] * xv[0].x + cr[n][1] * xv[1].x + cr[n][2] * xv[2].x + cr[n][3] * xv[3].x;
            o.y = cr[n][0] * xv[0].y + cr[n][1] * xv[1].y + cr[n][2] * xv[2].y + cr[n][3] * xv[3].y;
            o.z = cr[n][0] * xv[0].z + cr[n][1] * xv[1].z + cr[n][2] * xv[2].z + cr[n][3] * xv[3].z;
            o.w = cr[n][0] * xv[0].w + cr[n][1] * xv[1].w + cr[n][2] * xv[2].w + cr[n][3] * xv[3].w;
            __stcs(&orow[n * 256 + col], o);
        }
    }
}

// ---------------------------------------------------------------------------
// pure dots chunk (grid CHUNK_DOTS)
// ---------------------------------------------------------------------------
__global__ __launch_bounds__(128)
void mhc_dots_chunk(const float* __restrict__ x,
                    const float* __restrict__ read_in,  const float* __restrict__ a_ri,
                    const float* __restrict__ write_out, const float* __restrict__ a_wo,
                    const float* __restrict__ stream_mixing, const float* __restrict__ a_sm,
                    int dots_base) {
    extern __shared__ char smc[];
    dots_body(smc, x, read_in, a_ri, write_out, a_wo, stream_mixing, a_sm,
              dots_base + blockIdx.x);
}

// ---------------------------------------------------------------------------
// mixed chunk: 64 dots CTAs (bid%17==0) interleaved with 1024 k3 CTAs.
// grid = 1088 = 64*17. k3 CTAs read g_C written by the PREVIOUS launch, so
// the kernel boundary provides all ordering.
// ---------------------------------------------------------------------------
__global__ __launch_bounds__(128)
void mhc_mixed(const float* __restrict__ x, float* __restrict__ out,
               const float* __restrict__ read_in,  const float* __restrict__ a_ri,
               const float* __restrict__ write_out, const float* __restrict__ a_wo,
               const float* __restrict__ stream_mixing, const float* __restrict__ a_sm,
               int dots_base, int k3_base_row) {
    extern __shared__ char smc[];
    const int bid = blockIdx.x;
    const int q = bid / 17, r = bid % 17;
    if (r == 0) {
        dots_body(smc, x, read_in, a_ri, write_out, a_wo, stream_mixing, a_sm,
                  dots_base + q);
    } else {
        const int k3_idx = q * 16 + (r - 1);          // 0..1023
        const int row = k3_base_row + k3_idx * 4 + (threadIdx.x >> 5);
        k3_warp(x, out, row, threadIdx.x & 31);
    }
}

// ---------------------------------------------------------------------------
// pure k3 chunk (grid K3_CTAS)
// ---------------------------------------------------------------------------
__global__ __launch_bounds__(128)
void mhc_k3_chunk(const float* __restrict__ x, float* __restrict__ out,
                  int base_row) {
    const int row = base_row + blockIdx.x * 4 + (threadIdx.x >> 5);
    k3_warp(x, out, row, threadIdx.x & 31);
}

extern "C" void kernel_launch(void* const* d_in, const int* in_sizes, int n_in,
                              void* d_out, int out_size) {
    const float* x         = (const float*)d_in[0];
    const float* read_in   = (const float*)d_in[1];
    const float* a_ri      = (const float*)d_in[2];
    const float* write_out = (const float*)d_in[3];
    const float* a_wo      = (const float*)d_in[4];
    const float* smix      = (const float*)d_in[5];
    const float* a_sm      = (const float*)d_in[6];
    const float* Wri       = (const float*)d_in[7];
    const float* Wwo       = (const float*)d_in[8];
    const float* Wsm       = (const float*)d_in[9];
    float* out = (float*)d_out;

    cudaFuncSetAttribute(mhc_dots_chunk,
                         cudaFuncAttributeMaxDynamicSharedMemorySize, SMEM_B);
    cudaFuncSetAttribute(mhc_mixed,
                         cudaFuncAttributeMaxDynamicSharedMemorySize, SMEM_B);

    wconv<<<128, 256>>>(Wri, Wwo, Wsm);

    // pipeline: dots(q0) | dots(q1)+k3(q0) | dots(q2)+k3(q1) | dots(q3)+k3(q2) | k3(q3)
    mhc_dots_chunk<<<CHUNK_DOTS, 128, SMEM_B>>>(
        x, read_in, a_ri, write_out, a_wo, smix, a_sm, 0);
    mhc_mixed<<<CHUNK_DOTS * 17, 128, SMEM_B>>>(
        x, out, read_in, a_ri, write_out, a_wo, smix, a_sm,
        CHUNK_DOTS * 1, CHUNK_ROWS * 0);
    mhc_mixed<<<CHUNK_DOTS * 17, 128, SMEM_B>>>(
        x, out, read_in, a_ri, write_out, a_wo, smix, a_sm,
        CHUNK_DOTS * 2, CHUNK_ROWS * 1);
    mhc_mixed<<<CHUNK_DOTS * 17, 128, SMEM_B>>>(
        x, out, read_in, a_ri, write_out, a_wo, smix, a_sm,
        CHUNK_DOTS * 3, CHUNK_ROWS * 2);
    mhc_k3_chunk<<<K3_CTAS, 128>>>(x, out, CHUNK_ROWS * 3);
}

// round 13
// speedup vs baseline: 1.7606x; 1.7606x over previous
#include <cuda_runtime.h>
#include <cuda_bf16.h>
#include <cstdint>

#define B_TOTAL  16384
#define K_DIM    4096
#define F_EPS    1.1920929e-07f

#define ROWS_CTA 64
#define KT       64
#define NTILES   (K_DIM / KT)          // 64
#define STAGES   4
#define SX_B     288
#define SW_B     144
#define X_STAGE_B (ROWS_CTA * SX_B)    // 18432
#define W_STAGE_B (32 * SW_B)          // 4608
#define STAGE_B   (X_STAGE_B + W_STAGE_B)  // 23040
#define SMEM_B    (STAGES * STAGE_B)   // 92160

#define NBLOCKS  (B_TOTAL / ROWS_CTA)  // 256

__device__ __nv_bfloat16 g_Wb[32 * K_DIM];
__device__ float g_C[B_TOTAL * 16];
__device__ int   g_flag[NBLOCKS];

__device__ __forceinline__ void ffma2(unsigned long long &acc,
                                      unsigned long long a,
                                      unsigned long long b) {
    asm("fma.rn.f32x2 %0, %1, %2, %0;" : "+l"(acc) : "l"(a), "l"(b));
}
__device__ __forceinline__ float hsum2(unsigned long long v) {
    return __uint_as_float((unsigned)(v & 0xffffffffull)) +
           __uint_as_float((unsigned)(v >> 32));
}
__device__ __forceinline__ void cp_async16(uint32_t saddr, const void* g) {
    asm volatile("cp.async.cg.shared.global [%0], [%1], 16;\n" :: "r"(saddr), "l"(g));
}
__device__ __forceinline__ void cp_commit() {
    asm volatile("cp.async.commit_group;\n");
}
template <int N>
__device__ __forceinline__ void cp_wait() {
    asm volatile("cp.async.wait_group %0;\n" :: "n"(N));
}
__device__ __forceinline__ uint32_t cvt_bf2(float lo, float hi) {
    uint32_t r;
    asm("cvt.rn.bf16x2.f32 %0, %1, %2;" : "=r"(r) : "f"(hi), "f"(lo));
    return r;
}
__device__ __forceinline__ void mma_bf16(float &c0, float &c1, float &c2, float &c3,
                                         uint32_t a0, uint32_t a1, uint32_t a2, uint32_t a3,
                                         uint32_t b0, uint32_t b1) {
    asm volatile(
        "mma.sync.aligned.m16n8k16.row.col.f32.bf16.bf16.f32 "
        "{%0,%1,%2,%3}, {%4,%5,%6,%7}, {%8,%9}, {%0,%1,%2,%3};"
        : "+f"(c0), "+f"(c1), "+f"(c2), "+f"(c3)
        : "r"(a0), "r"(a1), "r"(a2), "r"(a3), "r"(b0), "r"(b1));
}

// ---------------------------------------------------------------------------
// prepass: W fp32 -> bf16, and zero the ordering flags (every replay).
// ---------------------------------------------------------------------------
__global__ __launch_bounds__(256)
void wconv(const float* __restrict__ Wri, const float* __restrict__ Wwo,
           const float* __restrict__ Wsm) {
    const int gid = blockIdx.x * 256 + threadIdx.x;
    if (gid < NBLOCKS) g_flag[gid] = 0;
    const int base = gid * 4;   // grid 128 -> 131072 elems
    const int d = base / K_DIM;
    const int k = base % K_DIM;
    const float* wrow = (d < 8)  ? (Wri + d * K_DIM)
                      : (d < 16) ? (Wwo + (d - 8) * K_DIM)
                                 : (Wsm + (d - 16) * K_DIM);
    const float4 v = *(const float4*)(wrow + k);
    *(uint2*)(&g_Wb[d * K_DIM + k]) = make_uint2(cvt_bf2(v.x, v.y), cvt_bf2(v.z, v.w));
}

// ---------------------------------------------------------------------------
// Fused dots + flag-ordered k3 tail. Grid 256, block 256 (8 warps, 2 CTAs/SM,
// all 256 CTAs co-resident). CTA b: dots+Sinkhorn(block b) -> flag[b]=1 ->
// spin flag[(b+1)%256] -> k3 for block b+1's rows.
// Dots warp tile: 8 rows x 32 dots (A rows 8-15 zero).
// ---------------------------------------------------------------------------
__global__ __launch_bounds__(256)
void mhc_fused(const float* __restrict__ x, float* __restrict__ out,
               const float* __restrict__ read_in,  const float* __restrict__ a_ri,
               const float* __restrict__ write_out, const float* __restrict__ a_wo,
               const float* __restrict__ stream_mixing, const float* __restrict__ a_sm) {
    extern __shared__ char smc[];
    const int tid  = threadIdx.x;
    const int warp = tid >> 5;          // 0..7, owns rows warp*8..+7
    const int lane = tid & 31;
    const int bid  = blockIdx.x;
    const int row0 = bid * ROWS_CTA;

    const uint32_t sbase = (uint32_t)__cvta_generic_to_shared(smc);

    // per tile: x 64 rows x 16 quads = 1024 f4 (4/thr), W 32x8 chunks = 256 (1/thr)
    auto fetch = [&](int t) {
        const uint32_t st = sbase + (t & (STAGES - 1)) * STAGE_B;
        const int k0 = t * KT;
#pragma unroll
        for (int i = 0; i < 4; i++) {
            const int f = tid + i * 256;
            const int row = f >> 4, kq = f & 15;
            cp_async16(st + row * SX_B + kq * 16,
                       x + (size_t)(row0 + row) * K_DIM + k0 + kq * 4);
        }
        {
            const int d = tid >> 3, kc = tid & 7;
            cp_async16(st + X_STAGE_B + d * SW_B + kc * 16,
                       g_Wb + d * K_DIM + k0 + kc * 8);
        }
        cp_commit();
    };

    fetch(0);
    fetch(1);
    fetch(2);

    float c[4][4];
#pragma unroll
    for (int n = 0; n < 4; n++)
#pragma unroll
        for (int j = 0; j < 4; j++) c[n][j] = 0.0f;
    unsigned long long ssa = 0ull;

    const int g  = lane >> 2;     // 0..7 -> row warp*8+g
    const int cc = lane & 3;      // 0..3

    for (int t = 0; t < NTILES; t++) {
        cp_wait<STAGES - 2>();
        __syncthreads();
        if (t + 3 < NTILES) fetch(t + 3);

        const char* stage = smc + (t & (STAGES - 1)) * STAGE_B;
        const char* xs = stage;
        const char* ws = stage + X_STAGE_B;

#pragma unroll
        for (int s = 0; s < 4; s++) {
            const int kb = s * 16;
            const char* arow = xs + (warp * 8 + g) * SX_B + (kb + cc * 2) * 4;
            const float2 fa0 = *(const float2*)(arow);
            const float2 fa2 = *(const float2*)(arow + 32);
            const unsigned long long u0 = *(const unsigned long long*)&fa0;
            const unsigned long long u2 = *(const unsigned long long*)&fa2;
            ffma2(ssa, u0, u0);
            ffma2(ssa, u2, u2);

            const uint32_t a0 = cvt_bf2(fa0.x, fa0.y);
            const uint32_t a2 = cvt_bf2(fa2.x, fa2.y);
#pragma unroll
            for (int ng = 0; ng < 4; ng++) {
                const char* brow = ws + (ng * 8 + g) * SW_B + (kb + cc * 2) * 2;
                const uint32_t b0 = *(const uint32_t*)(brow);
                const uint32_t b1 = *(const uint32_t*)(brow + 16);
                mma_bf16(c[ng][0], c[ng][1], c[ng][2], c[ng][3],
                         a0, 0u, a2, 0u, b0, b1);
            }
        }
    }
    __syncthreads();   // stage smem reads done -> alias Hs/SSs

    float* Hs  = (float*)smc;                    // [64][32]
    float* SSs = (float*)(smc + 64 * 32 * 4);    // [64]

    {
        const int r = warp * 8 + g;
#pragma unroll
        for (int ng = 0; ng < 4; ng++) {
            const int d0 = ng * 8 + cc * 2;
            Hs[r * 32 + d0]     = c[ng][0];
            Hs[r * 32 + d0 + 1] = c[ng][1];
        }
        float va = hsum2(ssa);
        va += __shfl_xor_sync(0xffffffffu, va, 1);
        va += __shfl_xor_sync(0xffffffffu, va, 2);
        if (cc == 0) SSs[r] = va;
    }
    __syncthreads();

    // gates + Sinkhorn: one thread per row
    if (tid < ROWS_CTA) {
        const int r = tid;
        const float s = rsqrtf(SSs[r] * (1.0f / (float)K_DIM) + F_EPS);
        float h[32];
#pragma unroll
        for (int d = 0; d < 32; d++) h[d] = Hs[r * 32 + d] * s;

        const float ari = a_ri[0], awo = a_wo[0], asmix = a_sm[0];
        float riT[2][4], wo[4][2], p[4][4];
#pragma unroll
        for (int n = 0; n < 4; n++)
#pragma unroll
            for (int m = 0; m < 2; m++) {
                const float hri = ari * h[n * 2 + m] + read_in[n * 2 + m];
                riT[m][n] = 1.0f / (1.0f + expf(-hri));
                const float hwo = awo * h[8 + n * 2 + m] + write_out[n * 2 + m];
                wo[n][m] = 2.0f / (1.0f + expf(-hwo));
            }
#pragma unroll
        for (int i = 0; i < 4; i++)
#pragma unroll
            for (int j = 0; j < 4; j++)
                p[i][j] = expf(asmix * h[16 + i * 4 + j] + stream_mixing[i * 4 + j]);

        for (int it = 0; it < 20; it++) {
#pragma unroll
            for (int i = 0; i < 4; i++) {
                const float inv = 1.0f / (p[i][0] + p[i][1] + p[i][2] + p[i][3]);
#pragma unroll
                for (int j = 0; j < 4; j++) p[i][j] *= inv;
            }
#pragma unroll
            for (int j = 0; j < 4; j++) {
                const float inv = 1.0f / (p[0][j] + p[1][j] + p[2][j] + p[3][j]);
#pragma unroll
                for (int i = 0; i < 4; i++) p[i][j] *= inv;
            }
        }
#pragma unroll
        for (int n = 0; n < 4; n++)
#pragma unroll
            for (int j = 0; j < 4; j++)
                g_C[(size_t)(row0 + r) * 16 + n * 4 + j] =
                    wo[n][0] * riT[0][j] + wo[n][1] * riT[1][j] + p[n][j];
    }
    __syncthreads();

    // publish C for this block
    if (tid == 0) {
        __threadfence();
        *(volatile int*)&g_flag[bid] = 1;
    }

    // ---- k3 tail for partner block (bid+1)%256, flag-ordered ----
    const int pb = (bid + 1) & (NBLOCKS - 1);
    if (tid == 0) {
        while (*(volatile int*)&g_flag[pb] == 0) { __nanosleep(64); }
    }
    __syncthreads();
    __threadfence();   // acquire: order g_C reads after flag observation

#pragma unroll 1
    for (int rr = 0; rr < 8; rr++) {
        const int row = pb * ROWS_CTA + warp * 8 + rr;
        float cr[4][4];
#pragma unroll
        for (int n = 0; n < 4; n++)
#pragma unroll
            for (int j = 0; j < 4; j++)
                cr[n][j] = __ldcg(&g_C[(size_t)row * 16 + n * 4 + j]);

        const float4* xr = (const float4*)(x + (size_t)row * K_DIM);
        float4* orow = (float4*)(out + (size_t)row * K_DIM);

#pragma unroll
        for (int pch = 0; pch < 8; pch++) {
            const int col = pch * 32 + lane;
            float4 xv[4];
#pragma unroll
            for (int j = 0; j < 4; j++) xv[j] = __ldcs(&xr[j * 256 + col]);
#pragma unroll
            for (int n = 0; n < 4; n++) {
                float4 o;
                o.x = cr[n][0] * xv[0].x + cr[n][1] * xv[1].x + cr[n][2] * xv[2].x + cr[n][3] * xv[3].x;
                o.y = cr[n][0] * xv[0].y + cr[n][1] * xv[1].y + cr[n][2] * xv[2].y + cr[n][3] * xv[3].y;
                o.z = cr[n][0] * xv[0].z + cr[n][1] * xv[1].z + cr[n][2] * xv[2].z + cr[n][3] * xv[3].z;
                o.w = cr[n][0] * xv[0].w + cr[n][1] * xv[1].w + cr[n][2] * xv[2].w + cr[n][3] * xv[3].w;
                __stcs(&orow[n * 256 + col], o);
            }
        }
    }
}

extern "C" void kernel_launch(void* const* d_in, const int* in_sizes, int n_in,
                              void* d_out, int out_size) {
    const float* x         = (const float*)d_in[0];
    const float* read_in   = (const float*)d_in[1];
    const float* a_ri      = (const float*)d_in[2];
    const float* write_out = (const float*)d_in[3];
    const float* a_wo      = (const float*)d_in[4];
    const float* smix      = (const float*)d_in[5];
    const float* a_sm      = (const float*)d_in[6];
    const float* Wri       = (const float*)d_in[7];
    const float* Wwo       = (const float*)d_in[8];
    const float* Wsm       = (const float*)d_in[9];
    float* out = (float*)d_out;

    wconv<<<128, 256>>>(Wri, Wwo, Wsm);

    cudaFuncSetAttribute(mhc_fused, cudaFuncAttributeMaxDynamicSharedMemorySize,
                         SMEM_B);
    mhc_fused<<<NBLOCKS, 256, SMEM_B>>>(
        x, out, read_in, a_ri, write_out, a_wo, smix, a_sm);
}

// round 14
// speedup vs baseline: 1.9191x; 1.0900x over previous
#include <cuda_runtime.h>
#include <cuda_bf16.h>
#include <cstdint>

#define B_TOTAL  16384
#define K_DIM    4096
#define F_EPS    1.1920929e-07f

#define ROWS_CTA 64
#define KT       64
#define NTILES   (K_DIM / KT)          // 64
#define STAGES   4
#define SX_B     288
#define SW_B     144
#define X_STAGE_B (ROWS_CTA * SX_B)    // 18432
#define W_STAGE_B (32 * SW_B)          // 4608
#define STAGE_B   (X_STAGE_B + W_STAGE_B)  // 23040
#define SMEM_B    (STAGES * STAGE_B)   // 92160

#define NBLOCKS  (B_TOTAL / ROWS_CTA)  // 256

__device__ __nv_bfloat16 g_Wb[32 * K_DIM];
__device__ float g_C[B_TOTAL * 16];

__device__ __forceinline__ void ffma2(unsigned long long &acc,
                                      unsigned long long a,
                                      unsigned long long b) {
    asm("fma.rn.f32x2 %0, %1, %2, %0;" : "+l"(acc) : "l"(a), "l"(b));
}
__device__ __forceinline__ float hsum2(unsigned long long v) {
    return __uint_as_float((unsigned)(v & 0xffffffffull)) +
           __uint_as_float((unsigned)(v >> 32));
}
__device__ __forceinline__ void cp_async16(uint32_t saddr, const void* g) {
    asm volatile("cp.async.cg.shared.global [%0], [%1], 16;\n" :: "r"(saddr), "l"(g));
}
__device__ __forceinline__ void cp_commit() {
    asm volatile("cp.async.commit_group;\n");
}
template <int N>
__device__ __forceinline__ void cp_wait() {
    asm volatile("cp.async.wait_group %0;\n" :: "n"(N));
}
__device__ __forceinline__ uint32_t cvt_bf2(float lo, float hi) {
    uint32_t r;
    asm("cvt.rn.bf16x2.f32 %0, %1, %2;" : "=r"(r) : "f"(hi), "f"(lo));
    return r;
}
__device__ __forceinline__ void mma_bf16(float &c0, float &c1, float &c2, float &c3,
                                         uint32_t a0, uint32_t a1, uint32_t a2, uint32_t a3,
                                         uint32_t b0, uint32_t b1) {
    asm volatile(
        "mma.sync.aligned.m16n8k16.row.col.f32.bf16.bf16.f32 "
        "{%0,%1,%2,%3}, {%4,%5,%6,%7}, {%8,%9}, {%0,%1,%2,%3};"
        : "+f"(c0), "+f"(c1), "+f"(c2), "+f"(c3)
        : "r"(a0), "r"(a1), "r"(a2), "r"(a3), "r"(b0), "r"(b1));
}

// ---------------------------------------------------------------------------
// prepass: W fp32 -> bf16
// ---------------------------------------------------------------------------
__global__ __launch_bounds__(256)
void wconv(const float* __restrict__ Wri, const float* __restrict__ Wwo,
           const float* __restrict__ Wsm) {
    const int base = (blockIdx.x * 256 + threadIdx.x) * 4;   // grid 128
    const int d = base / K_DIM;
    const int k = base % K_DIM;
    const float* wrow = (d < 8)  ? (Wri + d * K_DIM)
                      : (d < 16) ? (Wwo + (d - 8) * K_DIM)
                                 : (Wsm + (d - 16) * K_DIM);
    const float4 v = *(const float4*)(wrow + k);
    *(uint2*)(&g_Wb[d * K_DIM + k]) = make_uint2(cvt_bf2(v.x, v.y), cvt_bf2(v.z, v.w));
}

// ---------------------------------------------------------------------------
// Dots kernel. Grid 256, block 256 (8 warps, 2 CTAs/SM). CTA = 64 rows.
// Warp tile: 8 rows x 32 dots (A rows 8-15 zero). KT=64, 4 stages, 3 in flight.
// (This body is the verified R13 dots phase, without the k3 tail.)
// ---------------------------------------------------------------------------
__global__ __launch_bounds__(256)
void mhc_dots(const float* __restrict__ x,
              const float* __restrict__ read_in,  const float* __restrict__ a_ri,
              const float* __restrict__ write_out, const float* __restrict__ a_wo,
              const float* __restrict__ stream_mixing, const float* __restrict__ a_sm) {
    extern __shared__ char smc[];
    const int tid  = threadIdx.x;
    const int warp = tid >> 5;          // 0..7, owns rows warp*8..+7
    const int lane = tid & 31;
    const int bid  = blockIdx.x;
    const int row0 = bid * ROWS_CTA;

    const uint32_t sbase = (uint32_t)__cvta_generic_to_shared(smc);

    // per tile: x 64 rows x 16 quads = 1024 f4 (4/thr), W 32x8 chunks = 256 (1/thr)
    auto fetch = [&](int t) {
        const uint32_t st = sbase + (t & (STAGES - 1)) * STAGE_B;
        const int k0 = t * KT;
#pragma unroll
        for (int i = 0; i < 4; i++) {
            const int f = tid + i * 256;
            const int row = f >> 4, kq = f & 15;
            cp_async16(st + row * SX_B + kq * 16,
                       x + (size_t)(row0 + row) * K_DIM + k0 + kq * 4);
        }
        {
            const int d = tid >> 3, kc = tid & 7;
            cp_async16(st + X_STAGE_B + d * SW_B + kc * 16,
                       g_Wb + d * K_DIM + k0 + kc * 8);
        }
        cp_commit();
    };

    fetch(0);
    fetch(1);
    fetch(2);

    float c[4][4];
#pragma unroll
    for (int n = 0; n < 4; n++)
#pragma unroll
        for (int j = 0; j < 4; j++) c[n][j] = 0.0f;
    unsigned long long ssa = 0ull;

    const int g  = lane >> 2;     // 0..7 -> row warp*8+g
    const int cc = lane & 3;      // 0..3

    for (int t = 0; t < NTILES; t++) {
        cp_wait<STAGES - 2>();
        __syncthreads();
        if (t + 3 < NTILES) fetch(t + 3);

        const char* stage = smc + (t & (STAGES - 1)) * STAGE_B;
        const char* xs = stage;
        const char* ws = stage + X_STAGE_B;

#pragma unroll
        for (int s = 0; s < 4; s++) {
            const int kb = s * 16;
            const char* arow = xs + (warp * 8 + g) * SX_B + (kb + cc * 2) * 4;
            const float2 fa0 = *(const float2*)(arow);
            const float2 fa2 = *(const float2*)(arow + 32);
            const unsigned long long u0 = *(const unsigned long long*)&fa0;
            const unsigned long long u2 = *(const unsigned long long*)&fa2;
            ffma2(ssa, u0, u0);
            ffma2(ssa, u2, u2);

            const uint32_t a0 = cvt_bf2(fa0.x, fa0.y);
            const uint32_t a2 = cvt_bf2(fa2.x, fa2.y);
#pragma unroll
            for (int ng = 0; ng < 4; ng++) {
                const char* brow = ws + (ng * 8 + g) * SW_B + (kb + cc * 2) * 2;
                const uint32_t b0 = *(const uint32_t*)(brow);
                const uint32_t b1 = *(const uint32_t*)(brow + 16);
                mma_bf16(c[ng][0], c[ng][1], c[ng][2], c[ng][3],
                         a0, 0u, a2, 0u, b0, b1);
            }
        }
    }
    __syncthreads();   // stage smem reads done -> alias Hs/SSs

    float* Hs  = (float*)smc;                    // [64][32]
    float* SSs = (float*)(smc + 64 * 32 * 4);    // [64]

    {
        const int r = warp * 8 + g;
#pragma unroll
        for (int ng = 0; ng < 4; ng++) {
            const int d0 = ng * 8 + cc * 2;
            Hs[r * 32 + d0]     = c[ng][0];
            Hs[r * 32 + d0 + 1] = c[ng][1];
        }
        float va = hsum2(ssa);
        va += __shfl_xor_sync(0xffffffffu, va, 1);
        va += __shfl_xor_sync(0xffffffffu, va, 2);
        if (cc == 0) SSs[r] = va;
    }
    __syncthreads();

    // gates + Sinkhorn: one thread per row
    if (tid < ROWS_CTA) {
        const int r = tid;
        const float s = rsqrtf(SSs[r] * (1.0f / (float)K_DIM) + F_EPS);
        float h[32];
#pragma unroll
        for (int d = 0; d < 32; d++) h[d] = Hs[r * 32 + d] * s;

        const float ari = a_ri[0], awo = a_wo[0], asmix = a_sm[0];
        float riT[2][4], wo[4][2], p[4][4];
#pragma unroll
        for (int n = 0; n < 4; n++)
#pragma unroll
            for (int m = 0; m < 2; m++) {
                const float hri = ari * h[n * 2 + m] + read_in[n * 2 + m];
                riT[m][n] = 1.0f / (1.0f + expf(-hri));
                const float hwo = awo * h[8 + n * 2 + m] + write_out[n * 2 + m];
                wo[n][m] = 2.0f / (1.0f + expf(-hwo));
            }
#pragma unroll
        for (int i = 0; i < 4; i++)
#pragma unroll
            for (int j = 0; j < 4; j++)
                p[i][j] = expf(asmix * h[16 + i * 4 + j] + stream_mixing[i * 4 + j]);

        for (int it = 0; it < 20; it++) {
#pragma unroll
            for (int i = 0; i < 4; i++) {
                const float inv = 1.0f / (p[i][0] + p[i][1] + p[i][2] + p[i][3]);
#pragma unroll
                for (int j = 0; j < 4; j++) p[i][j] *= inv;
            }
#pragma unroll
            for (int j = 0; j < 4; j++) {
                const float inv = 1.0f / (p[0][j] + p[1][j] + p[2][j] + p[3][j]);
#pragma unroll
                for (int i = 0; i < 4; i++) p[i][j] *= inv;
            }
        }
#pragma unroll
        for (int n = 0; n < 4; n++)
#pragma unroll
            for (int j = 0; j < 4; j++)
                g_C[(size_t)(row0 + r) * 16 + n * 4 + j] =
                    wo[n][0] * riT[0][j] + wo[n][1] * riT[1][j] + p[n][j];
    }
}

// ---------------------------------------------------------------------------
// K2: out[b, n*1024+d] = sum_j C_b[n][j] * x[b, j*1024+d]. One CTA per row.
// Streaming loads/stores. (Byte-identical to the proven R10 kernel.)
// ---------------------------------------------------------------------------
__global__ __launch_bounds__(256)
void k3_out(const float* __restrict__ x, float* __restrict__ out) {
    const int b = blockIdx.x;
    __shared__ float Cs[16];
    if (threadIdx.x < 16) Cs[threadIdx.x] = g_C[b * 16 + threadIdx.x];
    __syncthreads();

    const int ci = threadIdx.x;
    const float4* xb = (const float4*)(x + (size_t)b * K_DIM);
    float4* ob = (float4*)(out + (size_t)b * K_DIM);

    float4 xv[4];
#pragma unroll
    for (int j = 0; j < 4; j++) xv[j] = __ldcs(&xb[j * 256 + ci]);

#pragma unroll
    for (int n = 0; n < 4; n++) {
        const float c0 = Cs[n * 4 + 0], c1 = Cs[n * 4 + 1],
                    c2 = Cs[n * 4 + 2], c3 = Cs[n * 4 + 3];
        float4 o;
        o.x = c0 * xv[0].x + c1 * xv[1].x + c2 * xv[2].x + c3 * xv[3].x;
        o.y = c0 * xv[0].y + c1 * xv[1].y + c2 * xv[2].y + c3 * xv[3].y;
        o.z = c0 * xv[0].z + c1 * xv[1].z + c2 * xv[2].z + c3 * xv[3].z;
        o.w = c0 * xv[0].w + c1 * xv[1].w + c2 * xv[2].w + c3 * xv[3].w;
        __stcs(&ob[n * 256 + ci], o);
    }
}

extern "C" void kernel_launch(void* const* d_in, const int* in_sizes, int n_in,
                              void* d_out, int out_size) {
    const float* x         = (const float*)d_in[0];
    const float* read_in   = (const float*)d_in[1];
    const float* a_ri      = (const float*)d_in[2];
    const float* write_out = (const float*)d_in[3];
    const float* a_wo      = (const float*)d_in[4];
    const float* smix      = (const float*)d_in[5];
    const float* a_sm      = (const float*)d_in[6];
    const float* Wri       = (const float*)d_in[7];
    const float* Wwo       = (const float*)d_in[8];
    const float* Wsm       = (const float*)d_in[9];
    float* out = (float*)d_out;

    wconv<<<128, 256>>>(Wri, Wwo, Wsm);

    cudaFuncSetAttribute(mhc_dots, cudaFuncAttributeMaxDynamicSharedMemorySize,
                         SMEM_B);
    mhc_dots<<<NBLOCKS, 256, SMEM_B>>>(
        x, read_in, a_ri, write_out, a_wo, smix, a_sm);

    k3_out<<<B_TOTAL, 256>>>(x, out);
}

// round 16
// speedup vs baseline: 1.9264x; 1.0038x over previous
#include <cuda_runtime.h>
#include <cuda_bf16.h>
#include <cstdint>

#define B_TOTAL  16384
#define K_DIM    4096
#define F_EPS    1.1920929e-07f

#define ROWS_CTA 64
#define KT       64
#define NTILES   (K_DIM / KT)          // 64
#define STAGES   4
#define SX_B     288
#define SW_B     144
#define X_STAGE_B (ROWS_CTA * SX_B)    // 18432
#define W_STAGE_B (32 * SW_B)          // 4608
#define STAGE_B   (X_STAGE_B + W_STAGE_B)  // 23040
#define SMEM_B    (STAGES * STAGE_B)   // 92160

#define NBLOCKS  (B_TOTAL / ROWS_CTA)  // 256

__device__ __nv_bfloat16 g_Wb[32 * K_DIM];
__device__ float g_C[B_TOTAL * 16];

__device__ __forceinline__ void ffma2(unsigned long long &acc,
                                      unsigned long long a,
                                      unsigned long long b) {
    asm("fma.rn.f32x2 %0, %1, %2, %0;" : "+l"(acc) : "l"(a), "l"(b));
}
__device__ __forceinline__ float hsum2(unsigned long long v) {
    return __uint_as_float((unsigned)(v & 0xffffffffull)) +
           __uint_as_float((unsigned)(v >> 32));
}
__device__ __forceinline__ void cp_async16(uint32_t saddr, const void* g) {
    asm volatile("cp.async.cg.shared.global [%0], [%1], 16;\n" :: "r"(saddr), "l"(g));
}
__device__ __forceinline__ void cp_commit() {
    asm volatile("cp.async.commit_group;\n");
}
template <int N>
__device__ __forceinline__ void cp_wait() {
    asm volatile("cp.async.wait_group %0;\n" :: "n"(N));
}
__device__ __forceinline__ uint32_t cvt_bf2(float lo, float hi) {
    uint32_t r;
    asm("cvt.rn.bf16x2.f32 %0, %1, %2;" : "=r"(r) : "f"(hi), "f"(lo));
    return r;
}
__device__ __forceinline__ void mma_bf16(float &c0, float &c1, float &c2, float &c3,
                                         uint32_t a0, uint32_t a1, uint32_t a2, uint32_t a3,
                                         uint32_t b0, uint32_t b1) {
    asm volatile(
        "mma.sync.aligned.m16n8k16.row.col.f32.bf16.bf16.f32 "
        "{%0,%1,%2,%3}, {%4,%5,%6,%7}, {%8,%9}, {%0,%1,%2,%3};"
        : "+f"(c0), "+f"(c1), "+f"(c2), "+f"(c3)
        : "r"(a0), "r"(a1), "r"(a2), "r"(a3), "r"(b0), "r"(b1));
}

// ---------------------------------------------------------------------------
// prepass: W fp32 -> bf16
// ---------------------------------------------------------------------------
__global__ __launch_bounds__(256)
void wconv(const float* __restrict__ Wri, const float* __restrict__ Wwo,
           const float* __restrict__ Wsm) {
    const int base = (blockIdx.x * 256 + threadIdx.x) * 4;   // grid 128
    const int d = base / K_DIM;
    const int k = base % K_DIM;
    const float* wrow = (d < 8)  ? (Wri + d * K_DIM)
                      : (d < 16) ? (Wwo + (d - 8) * K_DIM)
                                 : (Wsm + (d - 16) * K_DIM);
    const float4 v = *(const float4*)(wrow + k);
    *(uint2*)(&g_Wb[d * K_DIM + k]) = make_uint2(cvt_bf2(v.x, v.y), cvt_bf2(v.z, v.w));
}

// ---------------------------------------------------------------------------
// Dots kernel. Grid 256, block 256 (8 warps, 2 CTAs/SM, all CTAs co-resident).
// CTA = 64 rows; warp tile 8 rows x 32 dots (A rows 8-15 zero).
// k-loop DESCENDING (4096 -> 0): all CTAs sweep k in lockstep, so L2 ends up
// holding x[:, 0:~2048] — exactly the columns k3 reads FIRST.
// FIX vs R15: exact tail waits (t==1 -> wait<=1, t==0 -> wait 0) and a full
// cp.async drain before aliasing Hs/SSs over stage 0 (a pending fetch(0)
// could otherwise overwrite SSs with negative x floats -> rsqrtf -> NaN).
// ---------------------------------------------------------------------------
__global__ __launch_bounds__(256)
void mhc_dots(const float* __restrict__ x,
              const float* __restrict__ read_in,  const float* __restrict__ a_ri,
              const float* __restrict__ write_out, const float* __restrict__ a_wo,
              const float* __restrict__ stream_mixing, const float* __restrict__ a_sm) {
    extern __shared__ char smc[];
    const int tid  = threadIdx.x;
    const int warp = tid >> 5;          // 0..7, owns rows warp*8..+7
    const int lane = tid & 31;
    const int bid  = blockIdx.x;
    const int row0 = bid * ROWS_CTA;

    const uint32_t sbase = (uint32_t)__cvta_generic_to_shared(smc);

    // per tile: x 64 rows x 16 quads = 1024 f4 (4/thr), W 32x8 chunks = 256 (1/thr)
    auto fetch = [&](int t) {
        const uint32_t st = sbase + (t & (STAGES - 1)) * STAGE_B;
        const int k0 = t * KT;
#pragma unroll
        for (int i = 0; i < 4; i++) {
            const int f = tid + i * 256;
            const int row = f >> 4, kq = f & 15;
            cp_async16(st + row * SX_B + kq * 16,
                       x + (size_t)(row0 + row) * K_DIM + k0 + kq * 4);
        }
        {
            const int d = tid >> 3, kc = tid & 7;
            cp_async16(st + X_STAGE_B + d * SW_B + kc * 16,
                       g_Wb + d * K_DIM + k0 + kc * 8);
        }
        cp_commit();
    };

    fetch(NTILES - 1);
    fetch(NTILES - 2);
    fetch(NTILES - 3);

    float c[4][4];
#pragma unroll
    for (int n = 0; n < 4; n++)
#pragma unroll
        for (int j = 0; j < 4; j++) c[n][j] = 0.0f;
    unsigned long long ssa = 0ull;

    const int g  = lane >> 2;     // 0..7 -> row warp*8+g
    const int cc = lane & 3;      // 0..3

    for (int tt = 0; tt < NTILES; tt++) {
        const int t = NTILES - 1 - tt;     // descending k
        // exact wait: guarantee fetch(t) has landed even in the tail where no
        // new groups are committed (fetch(1)/fetch(0) are the 2 most recent).
        if (t >= 2)      cp_wait<STAGES - 2>();
        else if (t == 1) cp_wait<1>();
        else             cp_wait<0>();
        __syncthreads();
        if (t - 3 >= 0) fetch(t - 3);

        const char* stage = smc + (t & (STAGES - 1)) * STAGE_B;
        const char* xs = stage;
        const char* ws = stage + X_STAGE_B;

#pragma unroll
        for (int s = 0; s < 4; s++) {
            const int kb = s * 16;
            const char* arow = xs + (warp * 8 + g) * SX_B + (kb + cc * 2) * 4;
            const float2 fa0 = *(const float2*)(arow);
            const float2 fa2 = *(const float2*)(arow + 32);
            const unsigned long long u0 = *(const unsigned long long*)&fa0;
            const unsigned long long u2 = *(const unsigned long long*)&fa2;
            ffma2(ssa, u0, u0);
            ffma2(ssa, u2, u2);

            const uint32_t a0 = cvt_bf2(fa0.x, fa0.y);
            const uint32_t a2 = cvt_bf2(fa2.x, fa2.y);
#pragma unroll
            for (int ng = 0; ng < 4; ng++) {
                const char* brow = ws + (ng * 8 + g) * SW_B + (kb + cc * 2) * 2;
                const uint32_t b0 = *(const uint32_t*)(brow);
                const uint32_t b1 = *(const uint32_t*)(brow + 16);
                mma_bf16(c[ng][0], c[ng][1], c[ng][2], c[ng][3],
                         a0, 0u, a2, 0u, b0, b1);
            }
        }
    }
    cp_wait<0>();      // drain ALL cp.async before reusing stage smem for Hs/SSs
    __syncthreads();

    float* Hs  = (float*)smc;                    // [64][32]  (aliases stage 0)
    float* SSs = (float*)(smc + 64 * 32 * 4);    // [64]

    {
        const int r = warp * 8 + g;
#pragma unroll
        for (int ng = 0; ng < 4; ng++) {
            const int d0 = ng * 8 + cc * 2;
            Hs[r * 32 + d0]     = c[ng][0];
            Hs[r * 32 + d0 + 1] = c[ng][1];
        }
        float va = hsum2(ssa);
        va += __shfl_xor_sync(0xffffffffu, va, 1);
        va += __shfl_xor_sync(0xffffffffu, va, 2);
        if (cc == 0) SSs[r] = va;
    }
    __syncthreads();

    // gates + Sinkhorn: one thread per row
    if (tid < ROWS_CTA) {
        const int r = tid;
        const float s = rsqrtf(SSs[r] * (1.0f / (float)K_DIM) + F_EPS);
        float h[32];
#pragma unroll
        for (int d = 0; d < 32; d++) h[d] = Hs[r * 32 + d] * s;

        const float ari = a_ri[0], awo = a_wo[0], asmix = a_sm[0];
        float riT[2][4], wo[4][2], p[4][4];
#pragma unroll
        for (int n = 0; n < 4; n++)
#pragma unroll
            for (int m = 0; m < 2; m++) {
                const float hri = ari * h[n * 2 + m] + read_in[n * 2 + m];
                riT[m][n] = 1.0f / (1.0f + expf(-hri));
                const float hwo = awo * h[8 + n * 2 + m] + write_out[n * 2 + m];
                wo[n][m] = 2.0f / (1.0f + expf(-hwo));
            }
#pragma unroll
        for (int i = 0; i < 4; i++)
#pragma unroll
            for (int j = 0; j < 4; j++)
                p[i][j] = expf(asmix * h[16 + i * 4 + j] + stream_mixing[i * 4 + j]);

        for (int it = 0; it < 20; it++) {
#pragma unroll
            for (int i = 0; i < 4; i++) {
                const float inv = 1.0f / (p[i][0] + p[i][1] + p[i][2] + p[i][3]);
#pragma unroll
                for (int j = 0; j < 4; j++) p[i][j] *= inv;
            }
#pragma unroll
            for (int j = 0; j < 4; j++) {
                const float inv = 1.0f / (p[0][j] + p[1][j] + p[2][j] + p[3][j]);
#pragma unroll
                for (int i = 0; i < 4; i++) p[i][j] *= inv;
            }
        }
#pragma unroll
        for (int n = 0; n < 4; n++)
#pragma unroll
            for (int j = 0; j < 4; j++)
                g_C[(size_t)(row0 + r) * 16 + n * 4 + j] =
                    wo[n][0] * riT[0][j] + wo[n][1] * riT[1][j] + p[n][j];
    }
}

// ---------------------------------------------------------------------------
// K2: out[b, n*1024+d] = sum_j C_b[n][j] * x[b, j*1024+d]. One CTA per row.
// Reads columns ascending — first touching the x[:, 0:2048] slice that the
// descending dots sweep left resident in L2.
// ---------------------------------------------------------------------------
__global__ __launch_bounds__(256)
void k3_out(const float* __restrict__ x, float* __restrict__ out) {
    const int b = blockIdx.x;
    __shared__ float Cs[16];
    if (threadIdx.x < 16) Cs[threadIdx.x] = g_C[b * 16 + threadIdx.x];
    __syncthreads();

    const int ci = threadIdx.x;
    const float4* xb = (const float4*)(x + (size_t)b * K_DIM);
    float4* ob = (float4*)(out + (size_t)b * K_DIM);

    float4 xv[4];
#pragma unroll
    for (int j = 0; j < 4; j++) xv[j] = __ldcs(&xb[j * 256 + ci]);

#pragma unroll
    for (int n = 0; n < 4; n++) {
        const float c0 = Cs[n * 4 + 0], c1 = Cs[n * 4 + 1],
                    c2 = Cs[n * 4 + 2], c3 = Cs[n * 4 + 3];
        float4 o;
        o.x = c0 * xv[0].x + c1 * xv[1].x + c2 * xv[2].x + c3 * xv[3].x;
        o.y = c0 * xv[0].y + c1 * xv[1].y + c2 * xv[2].y + c3 * xv[3].y;
        o.z = c0 * xv[0].z + c1 * xv[1].z + c2 * xv[2].z + c3 * xv[3].z;
        o.w = c0 * xv[0].w + c1 * xv[1].w + c2 * xv[2].w + c3 * xv[3].w;
        __stcs(&ob[n * 256 + ci], o);
    }
}

extern "C" void kernel_launch(void* const* d_in, const int* in_sizes, int n_in,
                              void* d_out, int out_size) {
    const float* x         = (const float*)d_in[0];
    const float* read_in   = (const float*)d_in[1];
    const float* a_ri      = (const float*)d_in[2];
    const float* write_out = (const float*)d_in[3];
    const float* a_wo      = (const float*)d_in[4];
    const float* smix      = (const float*)d_in[5];
    const float* a_sm      = (const float*)d_in[6];
    const float* Wri       = (const float*)d_in[7];
    const float* Wwo       = (const float*)d_in[8];
    const float* Wsm       = (const float*)d_in[9];
    float* out = (float*)d_out;

    wconv<<<128, 256>>>(Wri, Wwo, Wsm);

    cudaFuncSetAttribute(mhc_dots, cudaFuncAttributeMaxDynamicSharedMemorySize,
                         SMEM_B);
    mhc_dots<<<NBLOCKS, 256, SMEM_B>>>(
        x, read_in, a_ri, write_out, a_wo, smix, a_sm);

    k3_out<<<B_TOTAL, 256>>>(x, out);
}